// round 5
// baseline (speedup 1.0000x reference)
#include <cuda_runtime.h>
#include <cstddef>

// Problem: B=64, n_l=512, n_h=32, d_l=16, d_h=32
#define Bsz 64
#define NLc 512
#define NHc 32
#define DLc 16
#define KLc 1024   // NH*DH
#define INV_SCALE 0.17677669529663687f  // 1/sqrt(32)
#define FNI 16     // i's per CTA chunk

// Static scratch (no allocations allowed)
__device__ float g_S[Bsz * KLc];          // S[b][k*32+l]
__device__ float g_Uh[Bsz * KLc];         // U_h accumulator

// Packed fp32x2 FMA (sm_100+)
__device__ __forceinline__ float2 ffma2(float2 a, float2 b, float2 c) {
    float2 d;
    asm("{\n\t"
        ".reg .b64 ra, rb, rc, rd;\n\t"
        "mov.b64 ra, {%2, %3};\n\t"
        "mov.b64 rb, {%4, %5};\n\t"
        "mov.b64 rc, {%6, %7};\n\t"
        "fma.rn.f32x2 rd, ra, rb, rc;\n\t"
        "mov.b64 {%0, %1}, rd;\n\t"
        "}"
        : "=f"(d.x), "=f"(d.y)
        : "f"(a.x), "f"(a.y), "f"(b.x), "f"(b.y), "f"(c.x), "f"(c.y));
    return d;
}

__device__ __forceinline__ unsigned smem_u32(const void* p) {
    return (unsigned)__cvta_generic_to_shared(p);
}
#define CP_ASYNC16(dst, src) \
    asm volatile("cp.async.ca.shared.global [%0], [%1], 16;" ::"r"(dst), "l"(src))
#define CP_COMMIT() asm volatile("cp.async.commit_group;")
#define CP_WAIT1() asm volatile("cp.async.wait_group 1;" ::: "memory")
#define CP_WAIT0() asm volatile("cp.async.wait_group 0;" ::: "memory")

// ---------------------------------------------------------------------------
__global__ void k_zero() {
    const int t = blockIdx.x * blockDim.x + threadIdx.x;  // 0..16383
    const float4 z = make_float4(0.f, 0.f, 0.f, 0.f);
    *reinterpret_cast<float4*>(g_S + (size_t)t * 4) = z;
    *reinterpret_cast<float4*>(g_Uh + (size_t)t * 4) = z;
}

// ---------------------------------------------------------------------------
// Shared staging for the 1024-thread kernels.
// W smem layout: float offset = j*1024 + k*32 + (lq&1)*16 + (lq>>1)*4
//   -> warp w (k=w) LDS.128 hits 4 consecutive 16B chunks (conflict-free,
//      8-way broadcast across b-groups).
// ---------------------------------------------------------------------------
__device__ __forceinline__ void stage_w(const float* __restrict__ Wi,
                                        float* dst, int tx) {
#pragma unroll
    for (int r = 0; r < 4; r++) {
        const int idx = tx + r * 1024;             // float4 idx 0..4095
        const int k = idx >> 7, j = (idx >> 3) & 15, lq = idx & 7;
        const int off = j * 1024 + k * 32 + ((lq & 1) << 4) + ((lq >> 1) << 2);
        CP_ASYNC16(smem_u32(dst + off), Wi + (size_t)idx * 4);
    }
}
__device__ __forceinline__ void stage_u(const float* __restrict__ U,
                                        float* dst, int b0, int i, int tx) {
    if (tx < 64) {
        const int bb = tx >> 2, j4 = (tx & 3) * 4;
        CP_ASYNC16(smem_u32(dst + bb * 16 + j4),
                   U + (size_t)(b0 + bb) * 8192 + (size_t)i * 16 + j4);
    }
}

// ---------------------------------------------------------------------------
// Pass 1: S[b][k*32+l] = sum_{i,j} U[b,i*16+j] * W[i,k,j,l]
// Grid (32 i-chunks, 4 b-slices of 16), 1024 threads, 32 warps (k = warp id).
// ---------------------------------------------------------------------------
#define P1_FLOATS (2 * 16384 + 2 * 256)
#define P1_BYTES (P1_FLOATS * 4)        // 133120 B

__global__ void __launch_bounds__(1024, 1) k_pass1(const float* __restrict__ U,
                                                   const float* __restrict__ W) {
    extern __shared__ float sm[];
    float* Ws  = sm;                 // [2][16384]
    float* Usm = sm + 2 * 16384;     // [2][256]

    const int tx = threadIdx.x;
    const int w = tx >> 5;           // k = w
    const int lane = tx & 31;
    const int bg = lane >> 2;        // 8 b-groups of 2 b
    const int lg = lane & 3;         // l-octet group
    const int b0 = blockIdx.y * 16;
    const int i0 = blockIdx.x * FNI;
    const int c0 = w * 32 + lg * 4;  // chunk e=0
    const int c1 = c0 + 16;          // chunk e=1

    float2 acc[2][4];
#pragma unroll
    for (int bb = 0; bb < 2; bb++)
#pragma unroll
        for (int p = 0; p < 4; p++) acc[bb][p] = make_float2(0.f, 0.f);

    stage_w(W + (size_t)i0 * 16384, Ws, tx);
    stage_u(U, Usm, b0, i0, tx);
    CP_COMMIT();

    int s = 0;
    for (int it = 0; it < FNI; it++) {
        if (it + 1 < FNI) {
            stage_w(W + (size_t)(i0 + it + 1) * 16384, Ws + (s ^ 1) * 16384, tx);
            stage_u(U, Usm + (s ^ 1) * 256, b0, i0 + it + 1, tx);
            CP_COMMIT();
            CP_WAIT1();
        } else {
            CP_WAIT0();
        }
        __syncthreads();

        const float* Wb = Ws + s * 16384;
        const float* Ub = Usm + s * 256;
#pragma unroll
        for (int j0 = 0; j0 < 16; j0 += 4) {
            const float4 uA = *reinterpret_cast<const float4*>(Ub + (bg * 2 + 0) * 16 + j0);
            const float4 uB = *reinterpret_cast<const float4*>(Ub + (bg * 2 + 1) * 16 + j0);
            const float uja[4] = {uA.x, uA.y, uA.z, uA.w};
            const float ujb[4] = {uB.x, uB.y, uB.z, uB.w};
#pragma unroll
            for (int jj = 0; jj < 4; jj++) {
                const float* wj = Wb + (j0 + jj) * 1024;
                const float4 w0 = *reinterpret_cast<const float4*>(wj + c0);
                const float4 w1 = *reinterpret_cast<const float4*>(wj + c1);
                const float2 wp0 = make_float2(w0.x, w0.y);
                const float2 wp1 = make_float2(w0.z, w0.w);
                const float2 wp2 = make_float2(w1.x, w1.y);
                const float2 wp3 = make_float2(w1.z, w1.w);
                const float2 ua = make_float2(uja[jj], uja[jj]);
                const float2 ub = make_float2(ujb[jj], ujb[jj]);
                acc[0][0] = ffma2(ua, wp0, acc[0][0]);
                acc[0][1] = ffma2(ua, wp1, acc[0][1]);
                acc[0][2] = ffma2(ua, wp2, acc[0][2]);
                acc[0][3] = ffma2(ua, wp3, acc[0][3]);
                acc[1][0] = ffma2(ub, wp0, acc[1][0]);
                acc[1][1] = ffma2(ub, wp1, acc[1][1]);
                acc[1][2] = ffma2(ub, wp2, acc[1][2]);
                acc[1][3] = ffma2(ub, wp3, acc[1][3]);
            }
        }
        s ^= 1;
        __syncthreads();
    }
#pragma unroll
    for (int bb = 0; bb < 2; bb++) {
        float* dst = g_S + (size_t)(b0 + bg * 2 + bb) * KLc + w * 32 + lg * 8;
        atomicAdd(dst + 0, acc[bb][0].x);
        atomicAdd(dst + 1, acc[bb][0].y);
        atomicAdd(dst + 2, acc[bb][1].x);
        atomicAdd(dst + 3, acc[bb][1].y);
        atomicAdd(dst + 4, acc[bb][2].x);
        atomicAdd(dst + 5, acc[bb][2].y);
        atomicAdd(dst + 6, acc[bb][3].x);
        atomicAdd(dst + 7, acc[bb][3].y);
    }
}

// ---------------------------------------------------------------------------
// Fused pass 2: u_hat in regs -> logits dot S -> softmax -> C-weighted acc.
// Same thread mapping as pass1; S slice staged once (same swizzled layout).
// ---------------------------------------------------------------------------
#define FSM_US   (2 * 16384)             // Usm[2][256]
#define FSM_SS   (FSM_US + 512)          // Ss[16][1024]
#define FSM_ASM  (FSM_SS + 16384)        // Asm[16][33]
#define FSM_CSM  (FSM_ASM + 16 * 33)     // Csm[16][33]
#define FSM_TOT  (FSM_CSM + 16 * 33)
#define FSM_BYTES (FSM_TOT * 4)          // 202880 B

__global__ void __launch_bounds__(1024, 1)
k_fused(const float* __restrict__ U, const float* __restrict__ W) {
    extern __shared__ float sm[];
    float* Ws  = sm;                 // [2][16384]
    float* Usm = sm + 2 * 16384;     // [2][256]
    float* Ss  = sm + FSM_SS;        // [16][1024] swizzled like W rows
    float* Asm = sm + FSM_ASM;       // [16][33]
    float* Csm = sm + FSM_CSM;       // [16][33]

    const int tx = threadIdx.x;
    const int w = tx >> 5;           // k = w
    const int lane = tx & 31;
    const int bg = lane >> 2;
    const int lg = lane & 3;
    const int b0 = blockIdx.y * 16;
    const int i0 = blockIdx.x * FNI;
    const int c0 = w * 32 + lg * 4;
    const int c1 = c0 + 16;

    // stage S slice (once) + first W/U
#pragma unroll
    for (int r = 0; r < 4; r++) {
        const int idx = tx + r * 1024;           // float4 idx 0..4095
        const int bb = idx >> 8, c = idx & 255;  // c = k*8+lq
        const int k = c >> 3, lq = c & 7;
        const int off = bb * 1024 + k * 32 + ((lq & 1) << 4) + ((lq >> 1) << 2);
        CP_ASYNC16(smem_u32(Ss + off), g_S + (size_t)(b0 + bb) * KLc + (size_t)c * 4);
    }
    stage_w(W + (size_t)i0 * 16384, Ws, tx);
    stage_u(U, Usm, b0, i0, tx);
    CP_COMMIT();

    float2 acc[2][4];
#pragma unroll
    for (int bb = 0; bb < 2; bb++)
#pragma unroll
        for (int p = 0; p < 4; p++) acc[bb][p] = make_float2(0.f, 0.f);

    int s = 0;
    for (int it = 0; it < FNI; it++) {
        if (it + 1 < FNI) {
            stage_w(W + (size_t)(i0 + it + 1) * 16384, Ws + (s ^ 1) * 16384, tx);
            stage_u(U, Usm + (s ^ 1) * 256, b0, i0 + it + 1, tx);
            CP_COMMIT();
            CP_WAIT1();
        } else {
            CP_WAIT0();
        }
        __syncthreads();

        const float* Wb = Ws + s * 16384;
        const float* Ub = Usm + s * 256;

        float2 uh[2][4];
#pragma unroll
        for (int bb = 0; bb < 2; bb++)
#pragma unroll
            for (int p = 0; p < 4; p++) uh[bb][p] = make_float2(0.f, 0.f);
#pragma unroll
        for (int j0 = 0; j0 < 16; j0 += 4) {
            const float4 uA = *reinterpret_cast<const float4*>(Ub + (bg * 2 + 0) * 16 + j0);
            const float4 uB = *reinterpret_cast<const float4*>(Ub + (bg * 2 + 1) * 16 + j0);
            const float uja[4] = {uA.x, uA.y, uA.z, uA.w};
            const float ujb[4] = {uB.x, uB.y, uB.z, uB.w};
#pragma unroll
            for (int jj = 0; jj < 4; jj++) {
                const float* wj = Wb + (j0 + jj) * 1024;
                const float4 w0 = *reinterpret_cast<const float4*>(wj + c0);
                const float4 w1 = *reinterpret_cast<const float4*>(wj + c1);
                const float2 wp0 = make_float2(w0.x, w0.y);
                const float2 wp1 = make_float2(w0.z, w0.w);
                const float2 wp2 = make_float2(w1.x, w1.y);
                const float2 wp3 = make_float2(w1.z, w1.w);
                const float2 ua = make_float2(uja[jj], uja[jj]);
                const float2 ub = make_float2(ujb[jj], ujb[jj]);
                uh[0][0] = ffma2(ua, wp0, uh[0][0]);
                uh[0][1] = ffma2(ua, wp1, uh[0][1]);
                uh[0][2] = ffma2(ua, wp2, uh[0][2]);
                uh[0][3] = ffma2(ua, wp3, uh[0][3]);
                uh[1][0] = ffma2(ub, wp0, uh[1][0]);
                uh[1][1] = ffma2(ub, wp1, uh[1][1]);
                uh[1][2] = ffma2(ub, wp2, uh[1][2]);
                uh[1][3] = ffma2(ub, wp3, uh[1][3]);
            }
        }

        // logits over this thread's 8 l, reduce over lg (xor 1,2)
        float a[2];
#pragma unroll
        for (int bb = 0; bb < 2; bb++) {
            const float* sp = Ss + (bg * 2 + bb) * 1024;
            const float4 s0 = *reinterpret_cast<const float4*>(sp + c0);
            const float4 s1 = *reinterpret_cast<const float4*>(sp + c1);
            a[bb] = uh[bb][0].x * s0.x + uh[bb][0].y * s0.y
                  + uh[bb][1].x * s0.z + uh[bb][1].y * s0.w
                  + uh[bb][2].x * s1.x + uh[bb][2].y * s1.y
                  + uh[bb][3].x * s1.z + uh[bb][3].y * s1.w;
            a[bb] += __shfl_xor_sync(0xffffffffu, a[bb], 1);
            a[bb] += __shfl_xor_sync(0xffffffffu, a[bb], 2);
        }
        if (lg == 0) {
            Asm[(bg * 2 + 0) * 33 + w] = a[0];
            Asm[(bg * 2 + 1) * 33 + w] = a[1];
        }
        __syncthreads();

        // softmax: warps 0..15 own b-local rows, lane = k
        if (w < 16) {
            const float v = Asm[w * 33 + lane];
            float m = v;
#pragma unroll
            for (int o = 16; o; o >>= 1)
                m = fmaxf(m, __shfl_xor_sync(0xffffffffu, m, o));
            const float ev = __expf((v - m) * INV_SCALE);
            float ssum = ev;
#pragma unroll
            for (int o = 16; o; o >>= 1)
                ssum += __shfl_xor_sync(0xffffffffu, ssum, o);
            Csm[w * 33 + lane] = ev / ssum;
        }
        __syncthreads();

        // C-weighted accumulation
#pragma unroll
        for (int bb = 0; bb < 2; bb++) {
            const float cw = Csm[(bg * 2 + bb) * 33 + w];
            const float2 cc = make_float2(cw, cw);
#pragma unroll
            for (int p = 0; p < 4; p++)
                acc[bb][p] = ffma2(cc, uh[bb][p], acc[bb][p]);
        }
        s ^= 1;
    }

#pragma unroll
    for (int bb = 0; bb < 2; bb++) {
        float* dst = g_Uh + (size_t)(b0 + bg * 2 + bb) * KLc + w * 32 + lg * 8;
        atomicAdd(dst + 0, acc[bb][0].x);
        atomicAdd(dst + 1, acc[bb][0].y);
        atomicAdd(dst + 2, acc[bb][1].x);
        atomicAdd(dst + 3, acc[bb][1].y);
        atomicAdd(dst + 4, acc[bb][2].x);
        atomicAdd(dst + 5, acc[bb][2].y);
        atomicAdd(dst + 6, acc[bb][3].x);
        atomicAdd(dst + 7, acc[bb][3].y);
    }
}

// ---------------------------------------------------------------------------
// Squash: warp per (b,k) vector. grid 256 x 256 threads = 2048 warps.
// ---------------------------------------------------------------------------
__global__ void k_squash(float* __restrict__ out) {
    const int v = blockIdx.x * 8 + (threadIdx.x >> 5);  // 0..2047
    const int lane = threadIdx.x & 31;
    const float x = g_Uh[(size_t)v * 32 + lane];
    float ss = x * x;
#pragma unroll
    for (int o = 16; o; o >>= 1)
        ss += __shfl_xor_sync(0xffffffffu, ss, o);
    const float n = sqrtf(ss);
    const float coef = (1.f - 1.f / (expf(n) + 1e-20f)) / (n + 1e-20f);
    out[(size_t)v * 32 + lane] = x * coef;
}

// ---------------------------------------------------------------------------
extern "C" void kernel_launch(void* const* d_in, const int* in_sizes, int n_in,
                              void* d_out, int out_size) {
    const float* U = (const float*)d_in[0];
    const float* W = (const float*)d_in[1];
    float* out = (float*)d_out;

    cudaFuncSetAttribute(k_pass1, cudaFuncAttributeMaxDynamicSharedMemorySize,
                         P1_BYTES);
    cudaFuncSetAttribute(k_fused, cudaFuncAttributeMaxDynamicSharedMemorySize,
                         FSM_BYTES);

    k_zero<<<64, 256>>>();
    k_pass1<<<dim3(32, 4), 1024, P1_BYTES>>>(U, W);
    k_fused<<<dim3(32, 4), 1024, FSM_BYTES>>>(U, W);
    k_squash<<<256, 256>>>(out);
}

// round 6
// speedup vs baseline: 1.3372x; 1.3372x over previous
#include <cuda_runtime.h>
#include <cstddef>

// Problem: B=64, n_l=512, n_h=32, d_l=16, d_h=32
#define Bsz 64
#define NLc 512
#define NHc 32
#define DLc 16
#define KLc 1024   // NH*DH
#define INV_SCALE 0.17677669529663687f  // 1/sqrt(32)
#define FNI 16     // i's per CTA chunk

// Static scratch (no allocations allowed)
__device__ float g_S[Bsz * KLc];          // S[b][k*32+l]
__device__ float g_Uh[Bsz * KLc];         // U_h accumulator

// Packed fp32x2 FMA (sm_100+)
__device__ __forceinline__ float2 ffma2(float2 a, float2 b, float2 c) {
    float2 d;
    asm("{\n\t"
        ".reg .b64 ra, rb, rc, rd;\n\t"
        "mov.b64 ra, {%2, %3};\n\t"
        "mov.b64 rb, {%4, %5};\n\t"
        "mov.b64 rc, {%6, %7};\n\t"
        "fma.rn.f32x2 rd, ra, rb, rc;\n\t"
        "mov.b64 {%0, %1}, rd;\n\t"
        "}"
        : "=f"(d.x), "=f"(d.y)
        : "f"(a.x), "f"(a.y), "f"(b.x), "f"(b.y), "f"(c.x), "f"(c.y));
    return d;
}

__device__ __forceinline__ unsigned smem_u32(const void* p) {
    return (unsigned)__cvta_generic_to_shared(p);
}
#define CP_ASYNC16(dst, src) \
    asm volatile("cp.async.ca.shared.global [%0], [%1], 16;" ::"r"(dst), "l"(src))
#define CP_COMMIT() asm volatile("cp.async.commit_group;")
#define CP_WAIT1() asm volatile("cp.async.wait_group 1;" ::: "memory")
#define CP_WAIT0() asm volatile("cp.async.wait_group 0;" ::: "memory")

// ---------------------------------------------------------------------------
__global__ void k_zero() {
    const int t = blockIdx.x * blockDim.x + threadIdx.x;  // 0..16383
    const float4 z = make_float4(0.f, 0.f, 0.f, 0.f);
    *reinterpret_cast<float4*>(g_S + (size_t)t * 4) = z;
    *reinterpret_cast<float4*>(g_Uh + (size_t)t * 4) = z;
}

// ---------------------------------------------------------------------------
// Chunk swizzle: c = k*8 + lg*2 + e  ->  [k4..k1][e][k0][lg1 lg0]
// Each quarter-warp's LDS.128 hits 8 distinct bank groups (conflict-free,
// 4-way broadcast across b-groups).
// ---------------------------------------------------------------------------
__device__ __forceinline__ int wswz(int c) {
    const int k = c >> 3, lg = (c >> 1) & 3, e = c & 1;
    return ((k >> 1) << 4) | (e << 3) | ((k & 1) << 2) | lg;
}

__device__ __forceinline__ void f_stage_w(const float* __restrict__ Wi,
                                          float* dst, int tx) {
#pragma unroll
    for (int r = 0; r < 8; r++) {
        const int idx = tx + r * 512;          // float4 idx 0..4095
        const int k = idx >> 7, j = (idx >> 3) & 15, lq = idx & 7;
        const int c = k * 8 + lq;
        CP_ASYNC16(smem_u32(dst + j * 1024 + wswz(c) * 4),
                   Wi + (size_t)idx * 4);
    }
}
__device__ __forceinline__ void f_stage_u(const float* __restrict__ U,
                                          float* dst, int b0, int i, int tx) {
    if (tx < 64) {
        const int bb = tx >> 2, j4 = (tx & 3) * 4;
        CP_ASYNC16(smem_u32(dst + bb * 16 + j4),
                   U + (size_t)(b0 + bb) * 8192 + (size_t)i * 16 + j4);
    }
}

// ---------------------------------------------------------------------------
// Pass 1: S[b][k*32+l] = sum_{i,j} U[b,i*16+j] * W[i,k,j,l]
// Fused-style mapping: 512 thr, grid (32 i-chunks, 4 b-slices), wswz W layout,
// thread tile 4b x 1k x 8l, persistent register accumulation, REDs at end.
// ---------------------------------------------------------------------------
#define P1_FLOATS (2 * 16384 + 2 * 256)
#define P1_BYTES (P1_FLOATS * 4)        // 133120 B

__global__ void __launch_bounds__(512, 1) k_pass1(const float* __restrict__ U,
                                                  const float* __restrict__ W) {
    extern __shared__ float sm[];
    float* Ws  = sm;                 // [2][16384]
    float* Usm = sm + 2 * 16384;     // [2][256]

    const int tx = threadIdx.x;
    const int w = tx >> 5;
    const int lane = tx & 31;
    const int bg = lane >> 3;                    // 4 b-groups of 4 b
    const int kk = w * 2 + ((lane >> 2) & 1);    // k 0..31
    const int lg = lane & 3;                     // l-octet group
    const int b0 = blockIdx.y * 16;
    const int i0 = blockIdx.x * FNI;
    const int c0 = ((kk >> 1) << 4) | ((kk & 1) << 2) | lg;   // e=0
    const int c1 = c0 | 8;                                    // e=1

    float2 acc[4][4];
#pragma unroll
    for (int bb = 0; bb < 4; bb++)
#pragma unroll
        for (int p = 0; p < 4; p++) acc[bb][p] = make_float2(0.f, 0.f);

    f_stage_w(W + (size_t)i0 * 16384, Ws, tx);
    f_stage_u(U, Usm, b0, i0, tx);
    CP_COMMIT();

    int s = 0;
    for (int it = 0; it < FNI; it++) {
        if (it + 1 < FNI) {
            f_stage_w(W + (size_t)(i0 + it + 1) * 16384, Ws + (s ^ 1) * 16384, tx);
            f_stage_u(U, Usm + (s ^ 1) * 256, b0, i0 + it + 1, tx);
            CP_COMMIT();
            CP_WAIT1();
        } else {
            CP_WAIT0();
        }
        __syncthreads();

        const float* Wb = Ws + s * 16384;
        const float* Ub = Usm + s * 256;
#pragma unroll
        for (int j0 = 0; j0 < 16; j0 += 4) {
            float4 uq[4];
#pragma unroll
            for (int bb = 0; bb < 4; bb++)
                uq[bb] = *reinterpret_cast<const float4*>(Ub + (bg * 4 + bb) * 16 + j0);
#pragma unroll
            for (int jj = 0; jj < 4; jj++) {
                const float* wj = Wb + (j0 + jj) * 1024;
                const float4 w0 = *reinterpret_cast<const float4*>(wj + c0 * 4);
                const float4 w1 = *reinterpret_cast<const float4*>(wj + c1 * 4);
                const float2 wp0 = make_float2(w0.x, w0.y);
                const float2 wp1 = make_float2(w0.z, w0.w);
                const float2 wp2 = make_float2(w1.x, w1.y);
                const float2 wp3 = make_float2(w1.z, w1.w);
#pragma unroll
                for (int bb = 0; bb < 4; bb++) {
                    const float u = (jj == 0) ? uq[bb].x : (jj == 1) ? uq[bb].y
                                  : (jj == 2) ? uq[bb].z : uq[bb].w;
                    const float2 us = make_float2(u, u);
                    acc[bb][0] = ffma2(us, wp0, acc[bb][0]);
                    acc[bb][1] = ffma2(us, wp1, acc[bb][1]);
                    acc[bb][2] = ffma2(us, wp2, acc[bb][2]);
                    acc[bb][3] = ffma2(us, wp3, acc[bb][3]);
                }
            }
        }
        s ^= 1;
        __syncthreads();
    }
#pragma unroll
    for (int bb = 0; bb < 4; bb++) {
        float* dst = g_S + (size_t)(b0 + bg * 4 + bb) * KLc + kk * 32 + lg * 8;
        atomicAdd(dst + 0, acc[bb][0].x);
        atomicAdd(dst + 1, acc[bb][0].y);
        atomicAdd(dst + 2, acc[bb][1].x);
        atomicAdd(dst + 3, acc[bb][1].y);
        atomicAdd(dst + 4, acc[bb][2].x);
        atomicAdd(dst + 5, acc[bb][2].y);
        atomicAdd(dst + 6, acc[bb][3].x);
        atomicAdd(dst + 7, acc[bb][3].y);
    }
}

// ---------------------------------------------------------------------------
// Fused pass 2 (identical to R4 best): u_hat in regs -> logits dot S ->
// softmax -> C-weighted accumulate -> REDs
// ---------------------------------------------------------------------------
#define FSM_SS   (2 * 16384)            // after Ws[2][16384]
#define FSM_US   (FSM_SS + 16384)       // Usm[2][256]
#define FSM_ASM  (FSM_US + 512)         // Asm[16][33]
#define FSM_CSM  (FSM_ASM + 16 * 33)    // Csm[16][33]
#define FSM_TOT  (FSM_CSM + 16 * 33)
#define FSM_BYTES (FSM_TOT * 4)         // 202880 B

__global__ void __launch_bounds__(512, 1)
k_fused(const float* __restrict__ U, const float* __restrict__ W) {
    extern __shared__ float sm[];
    float* Ws  = sm;                 // [buf][j][1024 swizzled]
    float* Ss  = sm + FSM_SS;        // [bb][1024 swizzled]
    float* Usm = sm + FSM_US;        // [buf][bb*16+j]
    float* Asm = sm + FSM_ASM;       // [bb][33]
    float* Csm = sm + FSM_CSM;       // [bb][33]

    const int tx = threadIdx.x;
    const int w = tx >> 5;
    const int lane = tx & 31;
    const int bg = lane >> 3;
    const int kk = w * 2 + ((lane >> 2) & 1);
    const int lg = lane & 3;
    const int b0 = blockIdx.y * 16;
    const int i0 = blockIdx.x * FNI;
    const int c0 = ((kk >> 1) << 4) | ((kk & 1) << 2) | lg;
    const int c1 = c0 | 8;

    // stage S slice + first W/U
#pragma unroll
    for (int r = 0; r < 8; r++) {
        const int idx = tx + r * 512;
        const int bb = idx >> 8, c = idx & 255;
        CP_ASYNC16(smem_u32(Ss + bb * 1024 + wswz(c) * 4),
                   g_S + (size_t)(b0 + bb) * KLc + (size_t)c * 4);
    }
    f_stage_w(W + (size_t)i0 * 16384, Ws, tx);
    f_stage_u(U, Usm, b0, i0, tx);
    CP_COMMIT();

    float2 acc[4][4];
#pragma unroll
    for (int bb = 0; bb < 4; bb++)
#pragma unroll
        for (int p = 0; p < 4; p++) acc[bb][p] = make_float2(0.f, 0.f);

    int s = 0;
    for (int it = 0; it < FNI; it++) {
        if (it + 1 < FNI) {
            f_stage_w(W + (size_t)(i0 + it + 1) * 16384, Ws + (s ^ 1) * 16384, tx);
            f_stage_u(U, Usm + (s ^ 1) * 256, b0, i0 + it + 1, tx);
            CP_COMMIT();
            CP_WAIT1();
        } else {
            CP_WAIT0();
        }
        __syncthreads();

        const float* Wb = Ws + s * 16384;
        const float* Ub = Usm + s * 256;

        float2 uh[4][4];
#pragma unroll
        for (int bb = 0; bb < 4; bb++)
#pragma unroll
            for (int p = 0; p < 4; p++) uh[bb][p] = make_float2(0.f, 0.f);
#pragma unroll
        for (int j = 0; j < 16; j++) {
            const float* wj = Wb + j * 1024;
            const float4 w0 = *reinterpret_cast<const float4*>(wj + c0 * 4);
            const float4 w1 = *reinterpret_cast<const float4*>(wj + c1 * 4);
            const float2 wp0 = make_float2(w0.x, w0.y);
            const float2 wp1 = make_float2(w0.z, w0.w);
            const float2 wp2 = make_float2(w1.x, w1.y);
            const float2 wp3 = make_float2(w1.z, w1.w);
#pragma unroll
            for (int bb = 0; bb < 4; bb++) {
                const float u = Ub[(bg * 4 + bb) * 16 + j];
                const float2 us = make_float2(u, u);
                uh[bb][0] = ffma2(us, wp0, uh[bb][0]);
                uh[bb][1] = ffma2(us, wp1, uh[bb][1]);
                uh[bb][2] = ffma2(us, wp2, uh[bb][2]);
                uh[bb][3] = ffma2(us, wp3, uh[bb][3]);
            }
        }

        float a[4];
#pragma unroll
        for (int bb = 0; bb < 4; bb++) {
            const float* sp = Ss + (bg * 4 + bb) * 1024;
            const float4 s0 = *reinterpret_cast<const float4*>(sp + c0 * 4);
            const float4 s1 = *reinterpret_cast<const float4*>(sp + c1 * 4);
            a[bb] = uh[bb][0].x * s0.x + uh[bb][0].y * s0.y
                  + uh[bb][1].x * s0.z + uh[bb][1].y * s0.w
                  + uh[bb][2].x * s1.x + uh[bb][2].y * s1.y
                  + uh[bb][3].x * s1.z + uh[bb][3].y * s1.w;
        }
#pragma unroll
        for (int bb = 0; bb < 4; bb++) {
            a[bb] += __shfl_xor_sync(0xffffffffu, a[bb], 1);
            a[bb] += __shfl_xor_sync(0xffffffffu, a[bb], 2);
        }
        if (lg == 0) {
#pragma unroll
            for (int bb = 0; bb < 4; bb++)
                Asm[(bg * 4 + bb) * 33 + kk] = a[bb];
        }
        __syncthreads();

        {   // softmax: warp w owns b-local row w, lane = k
            const float v = Asm[w * 33 + lane];
            float m = v;
#pragma unroll
            for (int o = 16; o; o >>= 1)
                m = fmaxf(m, __shfl_xor_sync(0xffffffffu, m, o));
            const float ev = __expf((v - m) * INV_SCALE);
            float ssum = ev;
#pragma unroll
            for (int o = 16; o; o >>= 1)
                ssum += __shfl_xor_sync(0xffffffffu, ssum, o);
            Csm[w * 33 + lane] = ev / ssum;
        }
        __syncthreads();

#pragma unroll
        for (int bb = 0; bb < 4; bb++) {
            const float cw = Csm[(bg * 4 + bb) * 33 + kk];
            const float2 cc = make_float2(cw, cw);
#pragma unroll
            for (int p = 0; p < 4; p++)
                acc[bb][p] = ffma2(cc, uh[bb][p], acc[bb][p]);
        }
        s ^= 1;
    }

#pragma unroll
    for (int bb = 0; bb < 4; bb++) {
        float* dst = g_Uh + (size_t)(b0 + bg * 4 + bb) * KLc + kk * 32 + lg * 8;
        atomicAdd(dst + 0, acc[bb][0].x);
        atomicAdd(dst + 1, acc[bb][0].y);
        atomicAdd(dst + 2, acc[bb][1].x);
        atomicAdd(dst + 3, acc[bb][1].y);
        atomicAdd(dst + 4, acc[bb][2].x);
        atomicAdd(dst + 5, acc[bb][2].y);
        atomicAdd(dst + 6, acc[bb][3].x);
        atomicAdd(dst + 7, acc[bb][3].y);
    }
}

// ---------------------------------------------------------------------------
// Squash: warp per (b,k) vector.
// ---------------------------------------------------------------------------
__global__ void k_squash(float* __restrict__ out) {
    const int v = blockIdx.x * 8 + (threadIdx.x >> 5);  // 0..2047
    const int lane = threadIdx.x & 31;
    const float x = g_Uh[(size_t)v * 32 + lane];
    float ss = x * x;
#pragma unroll
    for (int o = 16; o; o >>= 1)
        ss += __shfl_xor_sync(0xffffffffu, ss, o);
    const float n = sqrtf(ss);
    const float coef = (1.f - 1.f / (expf(n) + 1e-20f)) / (n + 1e-20f);
    out[(size_t)v * 32 + lane] = x * coef;
}

// ---------------------------------------------------------------------------
extern "C" void kernel_launch(void* const* d_in, const int* in_sizes, int n_in,
                              void* d_out, int out_size) {
    const float* U = (const float*)d_in[0];
    const float* W = (const float*)d_in[1];
    float* out = (float*)d_out;

    cudaFuncSetAttribute(k_pass1, cudaFuncAttributeMaxDynamicSharedMemorySize,
                         P1_BYTES);
    cudaFuncSetAttribute(k_fused, cudaFuncAttributeMaxDynamicSharedMemorySize,
                         FSM_BYTES);

    k_zero<<<64, 256>>>();
    k_pass1<<<dim3(32, 4), 512, P1_BYTES>>>(U, W);
    k_fused<<<dim3(32, 4), 512, FSM_BYTES>>>(U, W);
    k_squash<<<256, 256>>>(out);
}

// round 7
// speedup vs baseline: 1.5809x; 1.1823x over previous
#include <cuda_runtime.h>
#include <cstddef>

// Problem: B=64, n_l=512, n_h=32, d_l=16, d_h=32
#define Bsz 64
#define NLc 512
#define NHc 32
#define DLc 16
#define KLc 1024   // NH*DH
#define INV_SCALE 0.17677669529663687f  // 1/sqrt(32)
#define FNI 16     // i's per CTA chunk

// Static scratch (no allocations allowed)
__device__ float g_S[Bsz * KLc];          // S[b][k*32+l]
__device__ float g_Uh[Bsz * KLc];         // U_h accumulator

// Packed fp32x2 FMA (sm_100+)
__device__ __forceinline__ float2 ffma2(float2 a, float2 b, float2 c) {
    float2 d;
    asm("{\n\t"
        ".reg .b64 ra, rb, rc, rd;\n\t"
        "mov.b64 ra, {%2, %3};\n\t"
        "mov.b64 rb, {%4, %5};\n\t"
        "mov.b64 rc, {%6, %7};\n\t"
        "fma.rn.f32x2 rd, ra, rb, rc;\n\t"
        "mov.b64 {%0, %1}, rd;\n\t"
        "}"
        : "=f"(d.x), "=f"(d.y)
        : "f"(a.x), "f"(a.y), "f"(b.x), "f"(b.y), "f"(c.x), "f"(c.y));
    return d;
}

__device__ __forceinline__ unsigned smem_u32(const void* p) {
    return (unsigned)__cvta_generic_to_shared(p);
}
#define CP_ASYNC16(dst, src) \
    asm volatile("cp.async.ca.shared.global [%0], [%1], 16;" ::"r"(dst), "l"(src))
#define CP_COMMIT() asm volatile("cp.async.commit_group;")
#define CP_WAIT1() asm volatile("cp.async.wait_group 1;" ::: "memory")
#define CP_WAIT0() asm volatile("cp.async.wait_group 0;" ::: "memory")

// U column rotation: store U[b][j] at col ((j + (b & 12)) & 15).
// Makes the per-op rotation distinct across conflicting lanes -> conflict-free.
#define UROT(b, j) (((j) + ((b) & 12)) & 15)

// ---------------------------------------------------------------------------
__global__ void k_zero() {
    const int t = blockIdx.x * blockDim.x + threadIdx.x;  // 0..16383
    const float4 z = make_float4(0.f, 0.f, 0.f, 0.f);
    *reinterpret_cast<float4*>(g_S + (size_t)t * 4) = z;
    *reinterpret_cast<float4*>(g_Uh + (size_t)t * 4) = z;
}

// ---------------------------------------------------------------------------
// Pass 1: S[b][k*32+l] = sum_{i,j} U[b,i*16+j] * W[i,k,j,l]
// Grid (8 k-tiles of 4, 32 i-chunks of 16): W read ONCE. 256 thr, 8 warps.
// Warp w: k = k0 + (w&3), b-half = w>>2. Lane: bg(3b) x lg(2b).
// Thread tile: 4 b x 1 k x 8 l.  W smem [j][kloc][l] -> conflict-free bcast.
// ---------------------------------------------------------------------------
#define P1W 2048                        // floats per W buffer (16j x 4k x 32l)
#define P1_FLOATS (2 * P1W + 2 * 1024)  // + U[2][64][16]
#define P1_BYTES (P1_FLOATS * 4)        // 24576 B

__device__ __forceinline__ void p1_stage(const float* __restrict__ U,
                                         const float* __restrict__ W,
                                         int i, int k0, int tx,
                                         float* Ws, float* Us) {
    {   // W tile: 512 float4, two per thread; dst [j][k][l] (transposed)
        const float* Wi = W + (size_t)i * 16384 + (size_t)k0 * 512;
#pragma unroll
        for (int r = 0; r < 2; r++) {
            const int v = tx + r * 256;      // 0..511
            const int k = v >> 7, j = (v >> 3) & 15, lq = v & 7;
            CP_ASYNC16(smem_u32(Ws + j * 128 + k * 32 + lq * 4),
                       Wi + k * 512 + j * 32 + lq * 4);
        }
    }
    {   // U tile: 64x16, one float4 per thread, rotated columns
        const int b = tx >> 2, j4 = (tx & 3) * 4;
        CP_ASYNC16(smem_u32(Us + b * 16 + UROT(b, j4)),
                   U + (size_t)b * 8192 + (size_t)i * 16 + j4);
    }
}

__global__ void __launch_bounds__(256, 2) k_pass1(const float* __restrict__ U,
                                                  const float* __restrict__ W) {
    extern __shared__ float sm[];
    float* Ws  = sm;                 // [2][2048]
    float* Usm = sm + 2 * P1W;       // [2][1024]

    const int tx = threadIdx.x;
    const int w = tx >> 5;
    const int lane = tx & 31;
    const int bg = lane >> 2;            // 8 b-groups of 4 b
    const int lg = lane & 3;             // l quad group
    const int kloc = w & 3;
    const int bhalf = w >> 2;
    const int k0 = blockIdx.x * 4;
    const int i0 = blockIdx.y * FNI;
    const int bbase = bhalf * 32 + bg * 4;
    const int c0 = kloc * 32 + lg * 4;   // e=0 chunk (float offset in j-row)
    const int c1 = c0 + 16;              // e=1

    float2 acc[4][4];
#pragma unroll
    for (int bb = 0; bb < 4; bb++)
#pragma unroll
        for (int p = 0; p < 4; p++) acc[bb][p] = make_float2(0.f, 0.f);

    p1_stage(U, W, i0, k0, tx, Ws, Usm);
    CP_COMMIT();

    int s = 0;
    for (int it = 0; it < FNI; it++) {
        if (it + 1 < FNI) {
            p1_stage(U, W, i0 + it + 1, k0, tx, Ws + (s ^ 1) * P1W,
                     Usm + (s ^ 1) * 1024);
            CP_COMMIT();
            CP_WAIT1();
        } else {
            CP_WAIT0();
        }
        __syncthreads();

        const float* Wb = Ws + s * P1W;
        const float* Ub = Usm + s * 1024;
#pragma unroll
        for (int j0 = 0; j0 < 16; j0 += 4) {
            float4 uq[4];
#pragma unroll
            for (int bb = 0; bb < 4; bb++) {
                const int b = bbase + bb;
                uq[bb] = *reinterpret_cast<const float4*>(Ub + b * 16 + UROT(b, j0));
            }
#pragma unroll
            for (int jj = 0; jj < 4; jj++) {
                const float* wj = Wb + (j0 + jj) * 128;
                const float4 w0 = *reinterpret_cast<const float4*>(wj + c0);
                const float4 w1 = *reinterpret_cast<const float4*>(wj + c1);
                const float2 wp0 = make_float2(w0.x, w0.y);
                const float2 wp1 = make_float2(w0.z, w0.w);
                const float2 wp2 = make_float2(w1.x, w1.y);
                const float2 wp3 = make_float2(w1.z, w1.w);
#pragma unroll
                for (int bb = 0; bb < 4; bb++) {
                    const float u = (jj == 0) ? uq[bb].x : (jj == 1) ? uq[bb].y
                                  : (jj == 2) ? uq[bb].z : uq[bb].w;
                    const float2 us = make_float2(u, u);
                    acc[bb][0] = ffma2(us, wp0, acc[bb][0]);
                    acc[bb][1] = ffma2(us, wp1, acc[bb][1]);
                    acc[bb][2] = ffma2(us, wp2, acc[bb][2]);
                    acc[bb][3] = ffma2(us, wp3, acc[bb][3]);
                }
            }
        }
        s ^= 1;
        __syncthreads();
    }
#pragma unroll
    for (int bb = 0; bb < 4; bb++) {
        float* dst = g_S + (size_t)(bbase + bb) * KLc + (k0 + kloc) * 32 + lg * 4;
        atomicAdd(dst + 0,  acc[bb][0].x);
        atomicAdd(dst + 1,  acc[bb][0].y);
        atomicAdd(dst + 2,  acc[bb][1].x);
        atomicAdd(dst + 3,  acc[bb][1].y);
        atomicAdd(dst + 16, acc[bb][2].x);
        atomicAdd(dst + 17, acc[bb][2].y);
        atomicAdd(dst + 18, acc[bb][3].x);
        atomicAdd(dst + 19, acc[bb][3].y);
    }
}

// ---------------------------------------------------------------------------
// Fused pass 2 (R4 structure + U column rotation): u_hat in regs -> logits
// dot S -> softmax -> C-weighted accumulate -> REDs
// ---------------------------------------------------------------------------
__device__ __forceinline__ int wswz(int c) {
    const int k = c >> 3, lg = (c >> 1) & 3, e = c & 1;
    return ((k >> 1) << 4) | (e << 3) | ((k & 1) << 2) | lg;
}

#define FSM_SS   (2 * 16384)            // after Ws[2][16384]
#define FSM_US   (FSM_SS + 16384)       // Usm[2][256]
#define FSM_ASM  (FSM_US + 512)         // Asm[16][33]
#define FSM_CSM  (FSM_ASM + 16 * 33)    // Csm[16][33]
#define FSM_TOT  (FSM_CSM + 16 * 33)
#define FSM_BYTES (FSM_TOT * 4)         // 202880 B

__device__ __forceinline__ void f_stage_w(const float* __restrict__ Wi,
                                          float* dst, int tx) {
#pragma unroll
    for (int r = 0; r < 8; r++) {
        const int idx = tx + r * 512;          // float4 idx 0..4095
        const int k = idx >> 7, j = (idx >> 3) & 15, lq = idx & 7;
        const int c = k * 8 + lq;
        CP_ASYNC16(smem_u32(dst + j * 1024 + wswz(c) * 4),
                   Wi + (size_t)idx * 4);
    }
}
__device__ __forceinline__ void f_stage_u(const float* __restrict__ U,
                                          float* dst, int b0, int i, int tx) {
    if (tx < 64) {
        const int bb = tx >> 2, j4 = (tx & 3) * 4;
        CP_ASYNC16(smem_u32(dst + bb * 16 + UROT(bb, j4)),
                   U + (size_t)(b0 + bb) * 8192 + (size_t)i * 16 + j4);
    }
}

__global__ void __launch_bounds__(512, 1)
k_fused(const float* __restrict__ U, const float* __restrict__ W) {
    extern __shared__ float sm[];
    float* Ws  = sm;                 // [buf][j][1024 swizzled]
    float* Ss  = sm + FSM_SS;        // [bb][1024 swizzled]
    float* Usm = sm + FSM_US;        // [buf][b*16 + rotated col]
    float* Asm = sm + FSM_ASM;       // [bb][33]
    float* Csm = sm + FSM_CSM;       // [bb][33]

    const int tx = threadIdx.x;
    const int w = tx >> 5;
    const int lane = tx & 31;
    const int bg = lane >> 3;
    const int kk = w * 2 + ((lane >> 2) & 1);
    const int lg = lane & 3;
    const int b0 = blockIdx.y * 16;
    const int i0 = blockIdx.x * FNI;
    const int c0 = ((kk >> 1) << 4) | ((kk & 1) << 2) | lg;
    const int c1 = c0 | 8;

    // stage S slice + first W/U
#pragma unroll
    for (int r = 0; r < 8; r++) {
        const int idx = tx + r * 512;
        const int bb = idx >> 8, c = idx & 255;
        CP_ASYNC16(smem_u32(Ss + bb * 1024 + wswz(c) * 4),
                   g_S + (size_t)(b0 + bb) * KLc + (size_t)c * 4);
    }
    f_stage_w(W + (size_t)i0 * 16384, Ws, tx);
    f_stage_u(U, Usm, b0, i0, tx);
    CP_COMMIT();

    float2 acc[4][4];
#pragma unroll
    for (int bb = 0; bb < 4; bb++)
#pragma unroll
        for (int p = 0; p < 4; p++) acc[bb][p] = make_float2(0.f, 0.f);

    int s = 0;
    for (int it = 0; it < FNI; it++) {
        if (it + 1 < FNI) {
            f_stage_w(W + (size_t)(i0 + it + 1) * 16384, Ws + (s ^ 1) * 16384, tx);
            f_stage_u(U, Usm + (s ^ 1) * 256, b0, i0 + it + 1, tx);
            CP_COMMIT();
            CP_WAIT1();
        } else {
            CP_WAIT0();
        }
        __syncthreads();

        const float* Wb = Ws + s * 16384;
        const float* Ub = Usm + s * 256;

        float2 uh[4][4];
#pragma unroll
        for (int bb = 0; bb < 4; bb++)
#pragma unroll
            for (int p = 0; p < 4; p++) uh[bb][p] = make_float2(0.f, 0.f);
#pragma unroll
        for (int j = 0; j < 16; j++) {
            const float* wj = Wb + j * 1024;
            const float4 w0 = *reinterpret_cast<const float4*>(wj + c0 * 4);
            const float4 w1 = *reinterpret_cast<const float4*>(wj + c1 * 4);
            const float2 wp0 = make_float2(w0.x, w0.y);
            const float2 wp1 = make_float2(w0.z, w0.w);
            const float2 wp2 = make_float2(w1.x, w1.y);
            const float2 wp3 = make_float2(w1.z, w1.w);
#pragma unroll
            for (int bb = 0; bb < 4; bb++) {
                const int b = bg * 4 + bb;
                const float u = Ub[b * 16 + UROT(b, j)];
                const float2 us = make_float2(u, u);
                uh[bb][0] = ffma2(us, wp0, uh[bb][0]);
                uh[bb][1] = ffma2(us, wp1, uh[bb][1]);
                uh[bb][2] = ffma2(us, wp2, uh[bb][2]);
                uh[bb][3] = ffma2(us, wp3, uh[bb][3]);
            }
        }

        float a[4];
#pragma unroll
        for (int bb = 0; bb < 4; bb++) {
            const float* sp = Ss + (bg * 4 + bb) * 1024;
            const float4 s0 = *reinterpret_cast<const float4*>(sp + c0 * 4);
            const float4 s1 = *reinterpret_cast<const float4*>(sp + c1 * 4);
            a[bb] = uh[bb][0].x * s0.x + uh[bb][0].y * s0.y
                  + uh[bb][1].x * s0.z + uh[bb][1].y * s0.w
                  + uh[bb][2].x * s1.x + uh[bb][2].y * s1.y
                  + uh[bb][3].x * s1.z + uh[bb][3].y * s1.w;
        }
#pragma unroll
        for (int bb = 0; bb < 4; bb++) {
            a[bb] += __shfl_xor_sync(0xffffffffu, a[bb], 1);
            a[bb] += __shfl_xor_sync(0xffffffffu, a[bb], 2);
        }
        if (lg == 0) {
#pragma unroll
            for (int bb = 0; bb < 4; bb++)
                Asm[(bg * 4 + bb) * 33 + kk] = a[bb];
        }
        __syncthreads();

        {   // softmax: warp w owns b-local row w, lane = k
            const float v = Asm[w * 33 + lane];
            float m = v;
#pragma unroll
            for (int o = 16; o; o >>= 1)
                m = fmaxf(m, __shfl_xor_sync(0xffffffffu, m, o));
            const float ev = __expf((v - m) * INV_SCALE);
            float ssum = ev;
#pragma unroll
            for (int o = 16; o; o >>= 1)
                ssum += __shfl_xor_sync(0xffffffffu, ssum, o);
            Csm[w * 33 + lane] = ev / ssum;
        }
        __syncthreads();

#pragma unroll
        for (int bb = 0; bb < 4; bb++) {
            const float cw = Csm[(bg * 4 + bb) * 33 + kk];
            const float2 cc = make_float2(cw, cw);
#pragma unroll
            for (int p = 0; p < 4; p++)
                acc[bb][p] = ffma2(cc, uh[bb][p], acc[bb][p]);
        }
        s ^= 1;
    }

#pragma unroll
    for (int bb = 0; bb < 4; bb++) {
        float* dst = g_Uh + (size_t)(b0 + bg * 4 + bb) * KLc + kk * 32 + lg * 8;
        atomicAdd(dst + 0, acc[bb][0].x);
        atomicAdd(dst + 1, acc[bb][0].y);
        atomicAdd(dst + 2, acc[bb][1].x);
        atomicAdd(dst + 3, acc[bb][1].y);
        atomicAdd(dst + 4, acc[bb][2].x);
        atomicAdd(dst + 5, acc[bb][2].y);
        atomicAdd(dst + 6, acc[bb][3].x);
        atomicAdd(dst + 7, acc[bb][3].y);
    }
}

// ---------------------------------------------------------------------------
// Squash: warp per (b,k) vector.
// ---------------------------------------------------------------------------
__global__ void k_squash(float* __restrict__ out) {
    const int v = blockIdx.x * 8 + (threadIdx.x >> 5);  // 0..2047
    const int lane = threadIdx.x & 31;
    const float x = g_Uh[(size_t)v * 32 + lane];
    float ss = x * x;
#pragma unroll
    for (int o = 16; o; o >>= 1)
        ss += __shfl_xor_sync(0xffffffffu, ss, o);
    const float n = sqrtf(ss);
    const float coef = (1.f - 1.f / (expf(n) + 1e-20f)) / (n + 1e-20f);
    out[(size_t)v * 32 + lane] = x * coef;
}

// ---------------------------------------------------------------------------
extern "C" void kernel_launch(void* const* d_in, const int* in_sizes, int n_in,
                              void* d_out, int out_size) {
    const float* U = (const float*)d_in[0];
    const float* W = (const float*)d_in[1];
    float* out = (float*)d_out;

    cudaFuncSetAttribute(k_pass1, cudaFuncAttributeMaxDynamicSharedMemorySize,
                         P1_BYTES);
    cudaFuncSetAttribute(k_fused, cudaFuncAttributeMaxDynamicSharedMemorySize,
                         FSM_BYTES);

    k_zero<<<64, 256>>>();
    k_pass1<<<dim3(8, 32), 256, P1_BYTES>>>(U, W);
    k_fused<<<dim3(32, 4), 512, FSM_BYTES>>>(U, W);
    k_squash<<<256, 256>>>(out);
}